// round 6
// baseline (speedup 1.0000x reference)
#include <cuda_runtime.h>
#include <stdint.h>

// Problem shape is fixed: 32 images, 512x512, 1 channel, float32.
#define NIMG 32
#define H    512
#define WPX  512
#define WPR  16                       // 32-bit words per row (512/32)
#define NWORDS (NIMG * H * WPR)       // 262144 words = 1 MB
#define SEGROWS 128                   // output rows per CTA
#define GHOST 16                      // ghost rows each side (= substep count)
#define EROWS 160                     // extended rows held in smem
#define TPB 640                       // 160 rows x 4 quarter-strips

// Packed bit buffer (device global: no allocation allowed).
__device__ uint32_t g_bufA[NWORDS];

// ---------------------------------------------------------------------------
// Pack v3: one thread -> one 32-pixel word via 8 independent LDG.128 and
// thread-local bit assembly. No ballots (the previous version's serial
// 16-deep vote chain was the latency limiter).
// ---------------------------------------------------------------------------
__global__ void __launch_bounds__(256) pack_kernel(const float* __restrict__ in) {
    int w = blockIdx.x * blockDim.x + threadIdx.x;      // word index
    const float4* p = (const float4*)in + (size_t)w * 8;

    float4 f[8];
    #pragma unroll
    for (int j = 0; j < 8; ++j) f[j] = p[j];            // MLP = 8

    uint32_t r = 0;
    #pragma unroll
    for (int j = 0; j < 8; ++j) {
        r |= (f[j].x >= 0.5f ? (1u << (4 * j + 0)) : 0u);
        r |= (f[j].y >= 0.5f ? (1u << (4 * j + 1)) : 0u);
        r |= (f[j].z >= 0.5f ? (1u << (4 * j + 2)) : 0u);
        r |= (f[j].w >= 0.5f ? (1u << (4 * j + 3)) : 0u);
    }
    g_bufA[w] = r;
}

// ---------------------------------------------------------------------------
// Unpack v3: one thread -> 8 pixels, two STG.128, no I2F (bit * 0x3F800000).
// ---------------------------------------------------------------------------
__global__ void __launch_bounds__(256) unpack_kernel(float* __restrict__ out) {
    int tid = blockIdx.x * blockDim.x + threadIdx.x;    // 0 .. NPIX/8-1
    uint32_t w = g_bufA[tid >> 2];
    int sh = (tid & 3) * 8;
    float4 a, b;
    a.x = __uint_as_float(((w >> (sh + 0)) & 1u) * 0x3F800000u);
    a.y = __uint_as_float(((w >> (sh + 1)) & 1u) * 0x3F800000u);
    a.z = __uint_as_float(((w >> (sh + 2)) & 1u) * 0x3F800000u);
    a.w = __uint_as_float(((w >> (sh + 3)) & 1u) * 0x3F800000u);
    b.x = __uint_as_float(((w >> (sh + 4)) & 1u) * 0x3F800000u);
    b.y = __uint_as_float(((w >> (sh + 5)) & 1u) * 0x3F800000u);
    b.z = __uint_as_float(((w >> (sh + 6)) & 1u) * 0x3F800000u);
    b.w = __uint_as_float(((w >> (sh + 7)) & 1u) * 0x3F800000u);
    *(float4*)&out[tid * 8]     = a;
    *(float4*)&out[tid * 8 + 4] = b;
}

__device__ __forceinline__ uint32_t maj3(uint32_t a, uint32_t b, uint32_t c) {
    return (a & b) | (c & (a | b));    // 1 LOP3
}

// Zhang-Suen delete mask for one 32-pixel word, given the 8 neighbor masks.
// acnt==1 computed as acnt<=1 (valid since 2<=bcnt<=6 implies acnt>=1).
template<bool FIRST>
__device__ __forceinline__ uint32_t word_update(
    uint32_t mi, uint32_t P2, uint32_t P3, uint32_t P4, uint32_t P5,
    uint32_t P6, uint32_t P7, uint32_t P8, uint32_t P9)
{
    // ---- bcnt via CSA: need 2 <= bcnt <= 6 ----
    uint32_t sa = P2 ^ P3 ^ P4, ca = maj3(P2, P3, P4);
    uint32_t sb = P5 ^ P6 ^ P7, cb = maj3(P5, P6, P7);
    uint32_t sc = P8 ^ P9,      cc = P8 & P9;
    uint32_t S0s = sa ^ sb ^ sc, C1 = maj3(sa, sb, sc);
    uint32_t S1s = ca ^ cb ^ cc, C2 = maj3(ca, cb, cc);
    uint32_t ge2 = C1 | S1s | C2;
    uint32_t ge7 = C2 & ((C1 & S1s) | ((C1 ^ S1s) & S0s));

    // ---- acnt <= 1: all carries of the transition CSA are zero ----
    uint32_t t0 = ~P2 & P3, t1 = ~P3 & P4, t2 = ~P4 & P5, t3 = ~P5 & P6;
    uint32_t t4 = ~P6 & P7, t5 = ~P7 & P8, t6 = ~P8 & P9, t7 = ~P9 & P2;
    uint32_t aca = maj3(t0, t1, t2);
    uint32_t acb = maj3(t3, t4, t5);
    uint32_t acc = t6 & t7;
    uint32_t asa = t0 ^ t1 ^ t2;
    uint32_t asb = t3 ^ t4 ^ t5;
    uint32_t asc = t6 ^ t7;
    uint32_t A1  = maj3(asa, asb, asc);
    uint32_t ex1 = ~(A1 | aca | acb) & ~acc;

    // ---- c1 & c2 ----
    uint32_t inner;
    if (FIRST) inner = (P4 & P6) & (P2 | P8);
    else       inner = (P2 & P8) & (P4 | P6);

    uint32_t del = ge2 & ~ge7 & ex1 & ~inner;
    return mi & ~del;
}

// Compute 4 output words (quarter q of smem row r): S -> D.
// Caller guarantees 1 <= r <= EROWS-2.
template<bool FIRST>
__device__ __forceinline__ void strip4(
    const uint32_t* __restrict__ S, uint32_t* __restrict__ D, int r, int q)
{
    int base = r * WPR + q * 4;

    uint4 m4 = *(const uint4*)&S[base];
    uint4 u4 = *(const uint4*)&S[base - WPR];
    uint4 d4 = *(const uint4*)&S[base + WPR];
    uint32_t ml = q ? S[base - 1]       : 0u, mr = (q < 3) ? S[base + 4]       : 0u;
    uint32_t ul = q ? S[base - WPR - 1] : 0u, ur = (q < 3) ? S[base - WPR + 4] : 0u;
    uint32_t dl = q ? S[base + WPR - 1] : 0u, dr = (q < 3) ? S[base + WPR + 4] : 0u;

    uint32_t u[4] = {u4.x, u4.y, u4.z, u4.w};
    uint32_t m[4] = {m4.x, m4.y, m4.z, m4.w};
    uint32_t d[4] = {d4.x, d4.y, d4.z, d4.w};
    uint32_t o[4];

    #pragma unroll
    for (int j = 0; j < 4; ++j) {
        uint32_t up = u[j], mi = m[j], dn = d[j];
        uint32_t upl = j ? u[j - 1] : ul, upr = (j < 3) ? u[j + 1] : ur;
        uint32_t mil = j ? m[j - 1] : ml, mir = (j < 3) ? m[j + 1] : mr;
        uint32_t dnl = j ? d[j - 1] : dl, dnr = (j < 3) ? d[j + 1] : dr;

        uint32_t P2 = up;
        uint32_t P3 = __funnelshift_r(up, upr, 1);
        uint32_t P4 = __funnelshift_r(mi, mir, 1);
        uint32_t P5 = __funnelshift_r(dn, dnr, 1);
        uint32_t P6 = dn;
        uint32_t P7 = __funnelshift_l(dnl, dn, 1);
        uint32_t P8 = __funnelshift_l(mil, mi, 1);
        uint32_t P9 = __funnelshift_l(upl, up, 1);

        o[j] = word_update<FIRST>(mi, P2, P3, P4, P5, P6, P7, P8, P9);
    }

    *(uint4*)&D[base] = make_uint4(o[0], o[1], o[2], o[3]);
}

// ---------------------------------------------------------------------------
// Fully independent stencil kernel: NO inter-CTA synchronization.
// 128 CTAs (32 images x 4 segments). Each CTA holds its 128 rows plus
// 16 ghost rows per side (160 rows, smem idx r = extended row). The fake
// segment boundary corrupts at most 1 row per substep, so after 16 substeps
// rows 16..143 are exact. Substep k only computes the still-needed window
// [k, 159-k]. Out-of-image ghost rows are zero and stay zero (deletion-only).
// ---------------------------------------------------------------------------
__global__ void __launch_bounds__(TPB, 1) skeleton_kernel() {
    __shared__ uint32_t S0[EROWS * WPR];
    __shared__ uint32_t S1[EROWS * WPR];

    int tid = threadIdx.x;
    int r   = tid >> 2;                 // extended row 0..159
    int q   = tid & 3;                  // quarter-row
    int img = blockIdx.x >> 2;
    int seg = blockIdx.x & 3;

    // Load 160 rows (zero outside image).
    {
        int grow = seg * SEGROWS - GHOST + r;          // global image row
        uint4 v = make_uint4(0, 0, 0, 0);
        if (grow >= 0 && grow < H)
            v = *(const uint4*)&g_bufA[img * (H * WPR) + grow * WPR + q * 4];
        *(uint4*)&S0[r * WPR + q * 4] = v;
    }
    __syncthreads();

    #pragma unroll 1
    for (int k = 1; k <= 2 * GHOST; ++k) {
        bool active = (r >= k) && (r <= EROWS - 1 - k);
        if (k & 1) { if (active) strip4<true >(S0, S1, r, q); }
        else       { if (active) strip4<false>(S1, S0, r, q); }
        __syncthreads();
    }

    // Write back the exact region: extended rows 16..143.
    if (r >= GHOST && r < GHOST + SEGROWS) {
        int orow = seg * SEGROWS + (r - GHOST);
        *(uint4*)&g_bufA[img * (H * WPR) + orow * WPR + q * 4] =
            *(const uint4*)&S0[r * WPR + q * 4];
    }
}

extern "C" void kernel_launch(void* const* d_in, const int* in_sizes, int n_in,
                              void* d_out, int out_size) {
    (void)in_sizes; (void)n_in; (void)out_size;
    const float* in = (const float*)d_in[0];
    float* out = (float*)d_out;

    pack_kernel<<<NWORDS / 256, 256>>>(in);            // 1 word / thread

    skeleton_kernel<<<NIMG * 4, TPB>>>();

    const int NPIX = NIMG * H * WPX;                   // 8388608
    unpack_kernel<<<NPIX / (256 * 8), 256>>>(out);     // 8 px / thread
}

// round 7
// speedup vs baseline: 1.6542x; 1.6542x over previous
#include <cuda_runtime.h>
#include <stdint.h>

// Problem shape is fixed: 32 images, 512x512, 1 channel, float32.
#define NIMG 32
#define H    512
#define WPX  512
#define WPR  16                       // 32-bit words per row (512/32)
#define SEGROWS 128                   // rows per CTA
#define CLUSTER 4
#define TPB 512                       // 128 rows x 4 quarter-strips

__device__ __forceinline__ uint32_t maj3(uint32_t a, uint32_t b, uint32_t c) {
    return (a & b) | (c & (a | b));    // 1 LOP3
}

// DSMEM read of a shared-memory word from cluster CTA `rank`.
__device__ __forceinline__ uint32_t dsmem_ld(const uint32_t* p, uint32_t rank) {
    uint32_t a = (uint32_t)__cvta_generic_to_shared(p);
    uint32_t ra, v;
    asm volatile("mapa.shared::cluster.u32 %0, %1, %2;" : "=r"(ra) : "r"(a), "r"(rank));
    asm volatile("ld.shared::cluster.u32 %0, [%1];" : "=r"(v) : "r"(ra));
    return v;
}

__device__ __forceinline__ void cluster_barrier() {
    asm volatile("barrier.cluster.arrive.aligned;" ::: "memory");
    asm volatile("barrier.cluster.wait.aligned;" ::: "memory");
}

// Zhang-Suen delete mask for one 32-pixel word, given the 8 neighbor masks.
// acnt==1 computed as acnt<=1 (valid since 2<=bcnt<=6 implies acnt>=1).
template<bool FIRST>
__device__ __forceinline__ uint32_t word_update(
    uint32_t mi, uint32_t P2, uint32_t P3, uint32_t P4, uint32_t P5,
    uint32_t P6, uint32_t P7, uint32_t P8, uint32_t P9)
{
    // ---- bcnt via CSA: need 2 <= bcnt <= 6 ----
    uint32_t sa = P2 ^ P3 ^ P4, ca = maj3(P2, P3, P4);
    uint32_t sb = P5 ^ P6 ^ P7, cb = maj3(P5, P6, P7);
    uint32_t sc = P8 ^ P9,      cc = P8 & P9;
    uint32_t S0s = sa ^ sb ^ sc, C1 = maj3(sa, sb, sc);
    uint32_t S1s = ca ^ cb ^ cc, C2 = maj3(ca, cb, cc);
    uint32_t ge2 = C1 | S1s | C2;
    uint32_t ge7 = C2 & ((C1 & S1s) | ((C1 ^ S1s) & S0s));

    // ---- acnt <= 1: all carries of the transition CSA are zero ----
    uint32_t t0 = ~P2 & P3, t1 = ~P3 & P4, t2 = ~P4 & P5, t3 = ~P5 & P6;
    uint32_t t4 = ~P6 & P7, t5 = ~P7 & P8, t6 = ~P8 & P9, t7 = ~P9 & P2;
    uint32_t aca = maj3(t0, t1, t2);
    uint32_t acb = maj3(t3, t4, t5);
    uint32_t acc = t6 & t7;
    uint32_t asa = t0 ^ t1 ^ t2;
    uint32_t asb = t3 ^ t4 ^ t5;
    uint32_t asc = t6 ^ t7;
    uint32_t A1  = maj3(asa, asb, asc);
    uint32_t ex1 = ~(A1 | aca | acb) & ~acc;

    // ---- c1 & c2 ----
    uint32_t inner;
    if (FIRST) inner = (P4 & P6) & (P2 | P8);
    else       inner = (P2 & P8) & (P4 | P6);

    uint32_t del = ge2 & ~ge7 & ex1 & ~inner;
    return mi & ~del;
}

// Compute 4 output words (quarter q of smem row index i, 1<=i<=128): S -> D.
template<bool FIRST>
__device__ __forceinline__ void strip4(
    const uint32_t* __restrict__ S, uint32_t* __restrict__ D, int i, int q)
{
    int base = i * WPR + q * 4;

    uint4 m4 = *(const uint4*)&S[base];
    uint4 u4 = *(const uint4*)&S[base - WPR];
    uint4 d4 = *(const uint4*)&S[base + WPR];
    uint32_t ml = q ? S[base - 1]       : 0u, mr = (q < 3) ? S[base + 4]       : 0u;
    uint32_t ul = q ? S[base - WPR - 1] : 0u, ur = (q < 3) ? S[base - WPR + 4] : 0u;
    uint32_t dl = q ? S[base + WPR - 1] : 0u, dr = (q < 3) ? S[base + WPR + 4] : 0u;

    uint32_t u[4] = {u4.x, u4.y, u4.z, u4.w};
    uint32_t m[4] = {m4.x, m4.y, m4.z, m4.w};
    uint32_t d[4] = {d4.x, d4.y, d4.z, d4.w};
    uint32_t o[4];

    #pragma unroll
    for (int j = 0; j < 4; ++j) {
        uint32_t up = u[j], mi = m[j], dn = d[j];
        uint32_t upl = j ? u[j - 1] : ul, upr = (j < 3) ? u[j + 1] : ur;
        uint32_t mil = j ? m[j - 1] : ml, mir = (j < 3) ? m[j + 1] : mr;
        uint32_t dnl = j ? d[j - 1] : dl, dnr = (j < 3) ? d[j + 1] : dr;

        uint32_t P2 = up;
        uint32_t P3 = __funnelshift_r(up, upr, 1);
        uint32_t P4 = __funnelshift_r(mi, mir, 1);
        uint32_t P5 = __funnelshift_r(dn, dnr, 1);
        uint32_t P6 = dn;
        uint32_t P7 = __funnelshift_l(dnl, dn, 1);
        uint32_t P8 = __funnelshift_l(mil, mi, 1);
        uint32_t P9 = __funnelshift_l(upl, up, 1);

        o[j] = word_update<FIRST>(mi, P2, P3, P4, P5, P6, P7, P8, P9);
    }

    *(uint4*)&D[base] = make_uint4(o[0], o[1], o[2], o[3]);
}

// One substep: cluster barrier, pull halo rows from neighbors, compute.
// Smem layout: 130 rows x 16 words; local row r at index r+1; rows 0 and 129
// are ghost rows.
template<bool FIRST>
__device__ __forceinline__ void do_substep(
    const uint32_t* __restrict__ S, uint32_t* __restrict__ Dst,
    int rank, int tid)
{
    cluster_barrier();   // all CTAs' S (interior) complete cluster-wide

    if (tid < WPR) {     // top ghost <- prev rank's local row 127 (idx 128)
        uint32_t v = 0;
        if (rank > 0) v = dsmem_ld(&S[SEGROWS * WPR + tid], (uint32_t)(rank - 1));
        ((uint32_t*)S)[tid] = v;
    } else if (tid < 2 * WPR) {   // bottom ghost <- next rank's row 0 (idx 1)
        int w = tid - WPR;
        uint32_t v = 0;
        if (rank < CLUSTER - 1) v = dsmem_ld(&S[WPR + w], (uint32_t)(rank + 1));
        ((uint32_t*)S)[(SEGROWS + 1) * WPR + w] = v;
    }
    __syncthreads();

    strip4<FIRST>(S, Dst, 1 + (tid >> 2), tid & 3);
}

// ---------------------------------------------------------------------------
// Fully fused kernel: threshold+pack -> 16 substeps (cluster halo exchange)
// -> unpack+store. ONE launch. 128 CTAs (32 images x 4 segments),
// cluster = 4 CTAs = one image.
// ---------------------------------------------------------------------------
__global__ void __cluster_dims__(CLUSTER, 1, 1) __launch_bounds__(TPB, 1)
fused_skeleton_kernel(const float* __restrict__ in, float* __restrict__ out) {
    __shared__ uint32_t S0[(SEGROWS + 2) * WPR];
    __shared__ uint32_t S1[(SEGROWS + 2) * WPR];

    int tid  = threadIdx.x;
    int rank = blockIdx.x & (CLUSTER - 1);
    const size_t pxbase = (size_t)blockIdx.x * (SEGROWS * WPX);  // region origin

    // ---- Pack phase: ballot 128 rows into S0 rows idx 1..128 ----
    // 8 outer rounds x 16 rows; 16 independent loads per round (MLP=16).
    {
        int warpWord = tid >> 5;        // word within a row (16 warps)
        int lane     = tid & 31;
        const float* p = in + pxbase + tid;
        #pragma unroll 1
        for (int o = 0; o < 8; ++o) {
            float v[16];
            #pragma unroll
            for (int i = 0; i < 16; ++i)
                v[i] = p[(size_t)(o * 16 + i) * WPX];
            #pragma unroll
            for (int i = 0; i < 16; ++i) {
                uint32_t b = __ballot_sync(0xffffffffu, v[i] >= 0.5f);
                if (lane == 0) S0[(o * 16 + i + 1) * WPR + warpWord] = b;
            }
        }
    }
    // The cluster barrier inside the first do_substep orders these smem
    // writes (CTA-locally and cluster-wide) before any halo pull.

    // ---- 16 substeps (8 iterations x 2) ----
    #pragma unroll 1
    for (int it = 0; it < 8; ++it) {
        do_substep<true >(S0, S1, rank, tid);
        do_substep<false>(S1, S0, rank, tid);
    }
    __syncthreads();    // S0 final, visible CTA-wide

    // ---- Unpack phase: 32 float4 stores per thread ----
    {
        float4* o4 = (float4*)(out + pxbase);
        #pragma unroll 4
        for (int k = 0; k < 32; ++k) {
            int idx  = k * TPB + tid;            // float4 index in region
            int row  = idx >> 7;                 // 128 float4 per row
            int word = (idx & 127) >> 3;         // 8 float4 per word
            uint32_t w = S0[(row + 1) * WPR + word];
            int sh = (idx & 7) * 4;
            float4 f;
            f.x = __uint_as_float(((w >> (sh + 0)) & 1u) * 0x3F800000u);
            f.y = __uint_as_float(((w >> (sh + 1)) & 1u) * 0x3F800000u);
            f.z = __uint_as_float(((w >> (sh + 2)) & 1u) * 0x3F800000u);
            f.w = __uint_as_float(((w >> (sh + 3)) & 1u) * 0x3F800000u);
            o4[idx] = f;
        }
    }
}

extern "C" void kernel_launch(void* const* d_in, const int* in_sizes, int n_in,
                              void* d_out, int out_size) {
    (void)in_sizes; (void)n_in; (void)out_size;
    const float* in = (const float*)d_in[0];
    float* out = (float*)d_out;

    fused_skeleton_kernel<<<NIMG * CLUSTER, TPB>>>(in, out);
}

// round 8
// speedup vs baseline: 1.7268x; 1.0439x over previous
#include <cuda_runtime.h>
#include <stdint.h>

// Problem shape is fixed: 32 images, 512x512, 1 channel, float32.
#define NIMG 32
#define H    512
#define WPX  512
#define WPR  16                       // 32-bit words per row (512/32)
#define SEGROWS 128                   // output rows per CTA
#define GHOST 16                      // ghost rows each side (= substep count)
#define EROWS 160                     // extended rows held in smem
#define TPB 640                       // 160 rows x 4 quarter-strips

__device__ __forceinline__ uint32_t maj3(uint32_t a, uint32_t b, uint32_t c) {
    return (a & b) | (c & (a | b));    // 1 LOP3
}

// Zhang-Suen delete mask for one 32-pixel word, given the 8 neighbor masks.
// acnt==1 computed as acnt<=1 (valid since 2<=bcnt<=6 implies acnt>=1).
template<bool FIRST>
__device__ __forceinline__ uint32_t word_update(
    uint32_t mi, uint32_t P2, uint32_t P3, uint32_t P4, uint32_t P5,
    uint32_t P6, uint32_t P7, uint32_t P8, uint32_t P9)
{
    // ---- bcnt via CSA: need 2 <= bcnt <= 6 ----
    uint32_t sa = P2 ^ P3 ^ P4, ca = maj3(P2, P3, P4);
    uint32_t sb = P5 ^ P6 ^ P7, cb = maj3(P5, P6, P7);
    uint32_t sc = P8 ^ P9,      cc = P8 & P9;
    uint32_t S0s = sa ^ sb ^ sc, C1 = maj3(sa, sb, sc);
    uint32_t S1s = ca ^ cb ^ cc, C2 = maj3(ca, cb, cc);
    uint32_t ge2 = C1 | S1s | C2;
    uint32_t ge7 = C2 & ((C1 & S1s) | ((C1 ^ S1s) & S0s));

    // ---- acnt <= 1: all carries of the transition CSA are zero ----
    uint32_t t0 = ~P2 & P3, t1 = ~P3 & P4, t2 = ~P4 & P5, t3 = ~P5 & P6;
    uint32_t t4 = ~P6 & P7, t5 = ~P7 & P8, t6 = ~P8 & P9, t7 = ~P9 & P2;
    uint32_t aca = maj3(t0, t1, t2);
    uint32_t acb = maj3(t3, t4, t5);
    uint32_t acc = t6 & t7;
    uint32_t asa = t0 ^ t1 ^ t2;
    uint32_t asb = t3 ^ t4 ^ t5;
    uint32_t asc = t6 ^ t7;
    uint32_t A1  = maj3(asa, asb, asc);
    uint32_t ex1 = ~(A1 | aca | acb) & ~acc;

    // ---- c1 & c2 ----
    uint32_t inner;
    if (FIRST) inner = (P4 & P6) & (P2 | P8);
    else       inner = (P2 & P8) & (P4 | P6);

    uint32_t del = ge2 & ~ge7 & ex1 & ~inner;
    return mi & ~del;
}

// Compute 4 output words (quarter q of smem row r): S -> D.
// Caller guarantees 1 <= r <= EROWS-2.
template<bool FIRST>
__device__ __forceinline__ void strip4(
    const uint32_t* __restrict__ S, uint32_t* __restrict__ D, int r, int q)
{
    int base = r * WPR + q * 4;

    uint4 m4 = *(const uint4*)&S[base];
    uint4 u4 = *(const uint4*)&S[base - WPR];
    uint4 d4 = *(const uint4*)&S[base + WPR];
    uint32_t ml = q ? S[base - 1]       : 0u, mr = (q < 3) ? S[base + 4]       : 0u;
    uint32_t ul = q ? S[base - WPR - 1] : 0u, ur = (q < 3) ? S[base - WPR + 4] : 0u;
    uint32_t dl = q ? S[base + WPR - 1] : 0u, dr = (q < 3) ? S[base + WPR + 4] : 0u;

    uint32_t u[4] = {u4.x, u4.y, u4.z, u4.w};
    uint32_t m[4] = {m4.x, m4.y, m4.z, m4.w};
    uint32_t d[4] = {d4.x, d4.y, d4.z, d4.w};
    uint32_t o[4];

    #pragma unroll
    for (int j = 0; j < 4; ++j) {
        uint32_t up = u[j], mi = m[j], dn = d[j];
        uint32_t upl = j ? u[j - 1] : ul, upr = (j < 3) ? u[j + 1] : ur;
        uint32_t mil = j ? m[j - 1] : ml, mir = (j < 3) ? m[j + 1] : mr;
        uint32_t dnl = j ? d[j - 1] : dl, dnr = (j < 3) ? d[j + 1] : dr;

        uint32_t P2 = up;
        uint32_t P3 = __funnelshift_r(up, upr, 1);
        uint32_t P4 = __funnelshift_r(mi, mir, 1);
        uint32_t P5 = __funnelshift_r(dn, dnr, 1);
        uint32_t P6 = dn;
        uint32_t P7 = __funnelshift_l(dnl, dn, 1);
        uint32_t P8 = __funnelshift_l(mil, mi, 1);
        uint32_t P9 = __funnelshift_l(upl, up, 1);

        o[j] = word_update<FIRST>(mi, P2, P3, P4, P5, P6, P7, P8, P9);
    }

    *(uint4*)&D[base] = make_uint4(o[0], o[1], o[2], o[3]);
}

// ---------------------------------------------------------------------------
// Fully fused, sync-free-across-CTAs kernel:
//   ballot-pack 160 rows (128 + 16 ghosts/side, zero outside image)
//   -> 16 substeps with shrinking valid window [k, 159-k]
//   -> unpack rows 16..143 to gmem.
// 128 independent CTAs (32 images x 4 segments). No cluster, no DSMEM.
// Garbage from the fake segment boundary advances 1 row/substep, so after
// 16 substeps rows 16..143 are exact. Image-boundary ghost rows are zero
// and stay zero (deletion-only updates).
// ---------------------------------------------------------------------------
__global__ void __launch_bounds__(TPB, 1)
fused_skeleton_kernel(const float* __restrict__ in, float* __restrict__ out) {
    __shared__ uint32_t S0[EROWS * WPR];
    __shared__ uint32_t S1[EROWS * WPR];

    int tid = threadIdx.x;
    int img = blockIdx.x >> 2;
    int seg = blockIdx.x & 3;
    int segrow0 = seg * SEGROWS - GHOST;            // global row of ext row 0

    // ---- Pack phase: 20 warps x 8 extended rows, ballot per word ----
    {
        int warp = tid >> 5, lane = tid & 31;
        #pragma unroll 1
        for (int rr = 0; rr < 8; ++rr) {
            int r    = warp * 8 + rr;               // extended row 0..159
            int grow = segrow0 + r;
            bool valid = (grow >= 0) && (grow < H);
            const float* p = in + ((size_t)img * H + (valid ? grow : 0)) * WPX + lane;
            float v[16];
            #pragma unroll
            for (int i = 0; i < 16; ++i)            // MLP = 16
                v[i] = valid ? p[i * 32] : 0.0f;
            #pragma unroll
            for (int i = 0; i < 16; ++i) {
                uint32_t b = __ballot_sync(0xffffffffu, v[i] >= 0.5f);
                if (lane == 0) S0[r * WPR + i] = b;
            }
        }
    }
    __syncthreads();

    // ---- 16 substeps, shrinking window ----
    int r = tid >> 2;                 // extended row 0..159
    int q = tid & 3;                  // quarter-row
    #pragma unroll 1
    for (int k = 1; k <= 16; ++k) {
        bool active = (r >= k) && (r <= EROWS - 1 - k);
        if (k & 1) { if (active) strip4<true >(S0, S1, r, q); }
        else       { if (active) strip4<false>(S1, S0, r, q); }
        __syncthreads();
    }
    // k=16 is even: final state in S0; exact rows are 16..143.

    // ---- Unpack phase: rows 16..143 -> 16384 float4 stores ----
    {
        float4* o4 = (float4*)(out + ((size_t)img * H + seg * SEGROWS) * WPX);
        #pragma unroll 2
        for (int k2 = 0; k2 < 26; ++k2) {
            int idx = k2 * TPB + tid;               // float4 index in region
            if (idx < SEGROWS * 128) {
                int row  = idx >> 7;                // 128 float4 per row
                int word = (idx & 127) >> 3;        // 8 float4 per word
                uint32_t w = S0[(row + GHOST) * WPR + word];
                int sh = (idx & 7) * 4;
                float4 f;
                f.x = __uint_as_float(((w >> (sh + 0)) & 1u) * 0x3F800000u);
                f.y = __uint_as_float(((w >> (sh + 1)) & 1u) * 0x3F800000u);
                f.z = __uint_as_float(((w >> (sh + 2)) & 1u) * 0x3F800000u);
                f.w = __uint_as_float(((w >> (sh + 3)) & 1u) * 0x3F800000u);
                o4[idx] = f;
            }
        }
    }
}

extern "C" void kernel_launch(void* const* d_in, const int* in_sizes, int n_in,
                              void* d_out, int out_size) {
    (void)in_sizes; (void)n_in; (void)out_size;
    const float* in = (const float*)d_in[0];
    float* out = (float*)d_out;

    fused_skeleton_kernel<<<NIMG * 4, TPB>>>(in, out);
}